// round 11
// baseline (speedup 1.0000x reference)
#include <cuda_runtime.h>
#include <cuda_fp16.h>
#include <math.h>
#include <cstdint>

// ============================================================================
// Round 11: out = s_in @ Wfold + bfold (algebraic collapse, R2 derivation).
// R8's mainloop (best measured: 2 CTA/SM x 8 warps, 32-row batches, 4-stage
// 2KB cp.async rings, cross-batch pipelining) transplanted into ONE fused
// kernel: in-kernel W fold (first 64 CTAs) + device flag, and device-side
// counter reset by the last warp (no memset, no prep launch).
// ============================================================================

#define EPS_F 1e-6f

__device__ __half g_Wh[16384];    // fragment-major f16 W
__device__ int g_ctr  = 0;        // batch counter   (reset device-side at end)
__device__ int g_fold = 0;        // fold-done CTAs  (reset device-side at end)
__device__ int g_done = 0;        // finished warps  (reset device-side at end)

// ---------------- helpers ---------------------------------------------------
#define PACK_F16X2(d, hi, lo) \
    asm("cvt.rn.f16x2.f32 %0, %1, %2;" : "=r"(d) : "f"(hi), "f"(lo))

#define MMA_F16(c, a0, a1, a2, a3, b0, b1)                                      \
    asm volatile(                                                               \
        "mma.sync.aligned.m16n8k16.row.col.f32.f16.f16.f32 "                    \
        "{%0,%1,%2,%3}, {%4,%5,%6,%7}, {%8,%9}, {%0,%1,%2,%3};"                 \
        : "+f"((c)[0]), "+f"((c)[1]), "+f"((c)[2]), "+f"((c)[3])                \
        : "r"(a0), "r"(a1), "r"(a2), "r"(a3), "r"(b0), "r"(b1))

#define CP_ASYNC16(dst, src)                                                    \
    asm volatile("cp.async.cg.shared.global [%0], [%1], 16;"                    \
                 :: "r"(dst), "l"(src) : "memory")
#define CP_COMMIT()  asm volatile("cp.async.commit_group;" ::: "memory")
#define CP_WAIT(n)   asm volatile("cp.async.wait_group %0;" :: "n"(n) : "memory")

__device__ __forceinline__ uint32_t smem_u32(const void* p) {
    uint32_t a;
    asm("{ .reg .u64 t; cvta.to.shared.u64 t, %1; cvt.u32.u64 %0, t; }"
        : "=r"(a) : "l"(p));
    return a;
}

#define NCTA 296
#define TOTW (NCTA * 8)
// smem u32 layout: [0..8191] W frags | [8192..8255] bias | rings 8KB/warp
#define RING0_U32 8256
#define SMEM_U32  (RING0_U32 + 8 * 2048)    // 24640 u32 = 98560 B

// ---------------- fused persistent GEMM: [M,256] @ [256,64] -----------------
__global__ __launch_bounds__(256, 2)
void mma_all(const float* __restrict__ A, float* __restrict__ C,
             const float* __restrict__ Wv, const float* __restrict__ bv,
             int M, int NB, float nf) {
    extern __shared__ uint32_t sm[];
    const uint32_t sb = smem_u32(sm);

    const int t = threadIdx.x;
    const int wid = t >> 5;
    const int lane = t & 31;
    const int g  = lane >> 2;
    const int kq = lane & 3;
    const float scale = nf / (8.f * (nf + EPS_F));

    // ring: 4 stages x 2048 B per warp; thread slot g*64 + kq*16 within stage
    const uint32_t ring0 = sb + RING0_U32 * 4 + wid * 8192 + g * 64 + kq * 16;
    const float4* ringp = (const float4*)((const char*)sm +
                          RING0_U32 * 4 + wid * 8192 + g * 64 + kq * 16);
    // ringp in float4 units: stage*128 + rowgrp*32

#define SETUP_PTRS(p0, p1, p2, p3, base)                                        \
    const float* p0 = A + (size_t)min((base) + g,      M - 1) * 256 + kq * 4;   \
    const float* p1 = A + (size_t)min((base) + g + 8,  M - 1) * 256 + kq * 4;   \
    const float* p2 = A + (size_t)min((base) + g + 16, M - 1) * 256 + kq * 4;   \
    const float* p3 = A + (size_t)min((base) + g + 24, M - 1) * 256 + kq * 4

#define LOAD_CHUNK(p0, p1, p2, p3, c, st) do {                                  \
        uint32_t d_ = ring0 + (st) * 2048;                                      \
        CP_ASYNC16(d_,        p0 + (c) * 16);                                   \
        CP_ASYNC16(d_ + 512,  p1 + (c) * 16);                                   \
        CP_ASYNC16(d_ + 1024, p2 + (c) * 16);                                   \
        CP_ASYNC16(d_ + 1536, p3 + (c) * 16);                                   \
    } while (0)

    // ---- 1) grab first batch, issue A-prologue chunks 0..2 ----
    int b;
    if (lane == 0) b = atomicAdd(&g_ctr, 1);
    b = __shfl_sync(0xffffffffu, b, 0);
    const bool have = (b < NB);

    if (have) {
        SETUP_PTRS(i0, i1, i2, i3, b * 32);
        LOAD_CHUNK(i0, i1, i2, i3, 0, 0); CP_COMMIT();
        LOAD_CHUNK(i0, i1, i2, i3, 1, 1); CP_COMMIT();
        LOAD_CHUNK(i0, i1, i2, i3, 2, 2); CP_COMMIT();
    } else {
        CP_COMMIT(); CP_COMMIT(); CP_COMMIT();
    }

    // ---- 2) W fold: first 64 CTAs, one fragment-half per thread ----
    if (blockIdx.x < 64) {
        const int e = blockIdx.x * 256 + t;     // 0..16383
        const int k = e >> 6, n = e & 63;
        float s = 0.f;
#pragma unroll
        for (int h = 0; h < 8; h++) s += Wv[k * 512 + h * 64 + n];
        const int c  = k >> 4;
        const int r  = k & 15;
        const int kk = r >> 2;
        const int s2 = (r >> 1) & 1;
        const int w  = k & 1;
        const int j  = n >> 3;
        const int ln = (n & 7) * 4 + kk;
        g_Wh[((((c * 8 + j) * 32) + ln) * 2 + s2) * 2 + w] =
            __float2half_rn(s * scale);
        __threadfence();
        __syncthreads();
        if (t == 0) atomicAdd(&g_fold, 1);
    }

    // bias into smem (local, independent of fold flag)
    if (t < 64) {
        float bsum = 0.f;
#pragma unroll
        for (int h = 0; h < 8; h++) bsum += bv[h * 64 + t];
        ((float*)(sm + 8192))[t] = bsum * scale;
    }

    // ---- 3) wait for fold completion, then stage W (32 KB, L2-hot) ----
    if (t == 0) {
        while (((volatile int*)&g_fold)[0] < 64) __nanosleep(32);
    }
    __syncthreads();
    __threadfence();
    {
        uint32_t dst = sb + t * 16;
        const char* src = (const char*)g_Wh + t * 16;
#pragma unroll
        for (int i = 0; i < 8; i++)
            CP_ASYNC16(dst + i * 4096, src + i * 4096);
        CP_COMMIT();
    }
    CP_WAIT(0);
    __syncthreads();

    const uint2* Wp = ((const uint2*)sm) + lane;
    const float* bias_s = (const float*)(sm + 8192);

    // ---- 4) mainloop: identical to R8 ----
    if (have) {
        SETUP_PTRS(s0, s1, s2, s3, b * 32);
        const float *c0p = s0, *c1p = s1, *c2p = s2, *c3p = s3;

        for (;;) {
            int bn = NB;
            const float *n0p = c0p, *n1p = c1p, *n2p = c2p, *n3p = c3p;

            float acc0[8][4], acc1[8][4];
#pragma unroll
            for (int j = 0; j < 8; j++)
#pragma unroll
                for (int i = 0; i < 4; i++) { acc0[j][i] = 0.f; acc1[j][i] = 0.f; }

#pragma unroll
            for (int c = 0; c < 16; c++) {
                if (c == 12) {
                    if (lane == 0) bn = atomicAdd(&g_ctr, 1);
                    bn = __shfl_sync(0xffffffffu, bn, 0);
                }
                if (c == 13 && bn < NB) {
                    SETUP_PTRS(t0, t1, t2, t3, bn * 32);
                    n0p = t0; n1p = t1; n2p = t2; n3p = t3;
                }
                if (c < 13) {
                    LOAD_CHUNK(c0p, c1p, c2p, c3p, c + 3, (c + 3) & 3);
                } else if (bn < NB) {
                    LOAD_CHUNK(n0p, n1p, n2p, n3p, c - 13, (c + 3) & 3);
                }
                CP_COMMIT();
                CP_WAIT(3);

                const int st = c & 3;
                float4 q0 = ringp[st * 128];
                float4 q1 = ringp[st * 128 + 32];
                float4 q2 = ringp[st * 128 + 64];
                float4 q3 = ringp[st * 128 + 96];

                uint32_t a0, a1, a2, a3, b0, b1, b2, b3;
                PACK_F16X2(a0, q0.y, q0.x); PACK_F16X2(a1, q1.y, q1.x);
                PACK_F16X2(a2, q0.w, q0.z); PACK_F16X2(a3, q1.w, q1.z);
                PACK_F16X2(b0, q2.y, q2.x); PACK_F16X2(b1, q3.y, q3.x);
                PACK_F16X2(b2, q2.w, q2.z); PACK_F16X2(b3, q3.w, q3.z);
#pragma unroll
                for (int j = 0; j < 8; j++) {
                    uint2 w2 = Wp[(c * 8 + j) * 32];
                    MMA_F16(acc0[j], a0, a1, a2, a3, w2.x, w2.y);
                    MMA_F16(acc1[j], b0, b1, b2, b3, w2.x, w2.y);
                }
            }

            // epilogue: bias + store
            const int r0 = b * 32 + g;
            const int r1 = r0 + 8, r2 = r0 + 16, r3 = r0 + 24;
#pragma unroll
            for (int j = 0; j < 8; j++) {
                int col = j * 8 + kq * 2;
                float2 bb = *(const float2*)(bias_s + col);
                if (r0 < M)
                    *(float2*)(C + (size_t)r0 * 64 + col) =
                        make_float2(acc0[j][0] + bb.x, acc0[j][1] + bb.y);
                if (r1 < M)
                    *(float2*)(C + (size_t)r1 * 64 + col) =
                        make_float2(acc0[j][2] + bb.x, acc0[j][3] + bb.y);
                if (r2 < M)
                    *(float2*)(C + (size_t)r2 * 64 + col) =
                        make_float2(acc1[j][0] + bb.x, acc1[j][1] + bb.y);
                if (r3 < M)
                    *(float2*)(C + (size_t)r3 * 64 + col) =
                        make_float2(acc1[j][2] + bb.x, acc1[j][3] + bb.y);
            }

            if (bn >= NB) break;
            b = bn;
            c0p = n0p; c1p = n1p; c2p = n2p; c3p = n3p;
        }
    }
#undef LOAD_CHUNK
#undef SETUP_PTRS

    // ---- 5) last warp resets counters for the next graph replay ----
    if (lane == 0) {
        __threadfence();
        int d = atomicAdd(&g_done, 1);
        if (d == TOTW - 1) {
            g_ctr = 0;
            g_fold = 0;
            __threadfence();
            g_done = 0;
            __threadfence();
        }
    }
}

// ---------------- launch ----------------------------------------------------
extern "C" void kernel_launch(void* const* d_in, const int* in_sizes, int n_in,
                              void* d_out, int out_size) {
    const float* s_in = (const float*)d_in[1];
    const float* Wv   = (const float*)d_in[6];
    const float* bv   = (const float*)d_in[7];
    float* out = (float*)d_out;

    const int M = in_sizes[0] / 256;
    const int NB = (M + 31) / 32;

    const int SMEM = SMEM_U32 * 4;   // 98560 B -> 2 CTAs/SM
    cudaFuncSetAttribute(mma_all,
                         cudaFuncAttributeMaxDynamicSharedMemorySize, SMEM);
    mma_all<<<NCTA, 256, SMEM>>>(s_in, out, Wv, bv, M, NB, (float)M);
}

// round 12
// speedup vs baseline: 1.0364x; 1.0364x over previous
#include <cuda_runtime.h>
#include <cuda_fp16.h>
#include <math.h>
#include <cstdint>

// ============================================================================
// Round 12: out = s_in @ Wfold + bfold (algebraic collapse, R2 derivation).
// Single fused kernel (launch floor ~3us), fp16 m16n8k16, 2 CTA/SM x 8 warps,
// 32-row warp batches (R8 mainloop), with:
//  - fold LDGs first in fold CTAs; 4-chunk A prologue overlapping fold/spin
//  - 5-stage x 2KB per-warp cp.async ring (wait-depth 4 ~ 800cyc cover)
//  - device-side counter reset (no setup nodes)
// ============================================================================

#define EPS_F 1e-6f

__device__ __half g_Wh[16384];    // fragment-major f16 W
__device__ int g_ctr  = 0;        // batch counter
__device__ int g_fold = 0;        // fold-done CTA count
__device__ int g_done = 0;        // finished warps

// ---------------- helpers ---------------------------------------------------
#define PACK_F16X2(d, hi, lo) \
    asm("cvt.rn.f16x2.f32 %0, %1, %2;" : "=r"(d) : "f"(hi), "f"(lo))

#define MMA_F16(c, a0, a1, a2, a3, b0, b1)                                      \
    asm volatile(                                                               \
        "mma.sync.aligned.m16n8k16.row.col.f32.f16.f16.f32 "                    \
        "{%0,%1,%2,%3}, {%4,%5,%6,%7}, {%8,%9}, {%0,%1,%2,%3};"                 \
        : "+f"((c)[0]), "+f"((c)[1]), "+f"((c)[2]), "+f"((c)[3])                \
        : "r"(a0), "r"(a1), "r"(a2), "r"(a3), "r"(b0), "r"(b1))

#define CP_ASYNC16(dst, src)                                                    \
    asm volatile("cp.async.cg.shared.global [%0], [%1], 16;"                    \
                 :: "r"(dst), "l"(src) : "memory")
#define CP_COMMIT()  asm volatile("cp.async.commit_group;" ::: "memory")
#define CP_WAIT(n)   asm volatile("cp.async.wait_group %0;" :: "n"(n) : "memory")

__device__ __forceinline__ uint32_t smem_u32(const void* p) {
    uint32_t a;
    asm("{ .reg .u64 t; cvta.to.shared.u64 t, %1; cvt.u32.u64 %0, t; }"
        : "=r"(a) : "l"(p));
    return a;
}

#define NCTA 296
#define TOTW (NCTA * 8)
#define NSTG 5
// smem u32 layout: [0..8191] W frags | [8192..8255] bias | rings 10KB/warp
#define RING0_U32 8256
#define SMEM_U32  (RING0_U32 + 8 * (NSTG * 512))   // 28736 u32 = 114944 B

// ---------------- fused persistent GEMM: [M,256] @ [256,64] -----------------
__global__ __launch_bounds__(256, 2)
void mma_all(const float* __restrict__ A, float* __restrict__ C,
             const float* __restrict__ Wv, const float* __restrict__ bv,
             int M, int NB, float nf) {
    extern __shared__ uint32_t sm[];
    const uint32_t sb = smem_u32(sm);

    const int t = threadIdx.x;
    const int wid = t >> 5;
    const int lane = t & 31;
    const int g  = lane >> 2;
    const int kq = lane & 3;
    const float scale = nf / (8.f * (nf + EPS_F));
    const bool folder = (blockIdx.x < 64);

    // ---- 0) fold loads issued FIRST (critical chain for the whole grid) ----
    float fsum = 0.f;
    int fk = 0, fn = 0;
    if (folder) {
        const int e = blockIdx.x * 256 + t;     // 0..16383
        fk = e >> 6; fn = e & 63;
        const float* wp = Wv + fk * 512 + fn;
#pragma unroll
        for (int h = 0; h < 8; h++) fsum += wp[h * 64];
    }

    // ring: 5 stages x 2048 B per warp; thread slot g*64 + kq*16 within stage
    const uint32_t ring0 = sb + RING0_U32 * 4 + wid * (NSTG * 2048) +
                           g * 64 + kq * 16;
    const float4* ringp = (const float4*)((const char*)sm +
                          RING0_U32 * 4 + wid * (NSTG * 2048) +
                          g * 64 + kq * 16);
    // ringp in float4 units: stage*128 + rowgrp*32

#define SETUP_PTRS(p0, p1, p2, p3, base)                                        \
    const float* p0 = A + (size_t)min((base) + g,      M - 1) * 256 + kq * 4;   \
    const float* p1 = A + (size_t)min((base) + g + 8,  M - 1) * 256 + kq * 4;   \
    const float* p2 = A + (size_t)min((base) + g + 16, M - 1) * 256 + kq * 4;   \
    const float* p3 = A + (size_t)min((base) + g + 24, M - 1) * 256 + kq * 4

#define LOAD_CHUNK(p0, p1, p2, p3, c, st) do {                                  \
        uint32_t d_ = ring0 + (st) * 2048;                                      \
        CP_ASYNC16(d_,        p0 + (c) * 16);                                   \
        CP_ASYNC16(d_ + 512,  p1 + (c) * 16);                                   \
        CP_ASYNC16(d_ + 1024, p2 + (c) * 16);                                   \
        CP_ASYNC16(d_ + 1536, p3 + (c) * 16);                                   \
    } while (0)

    // ---- 1) grab first batch, issue A-prologue chunks 0..3 ----
    int b;
    if (lane == 0) b = atomicAdd(&g_ctr, 1);
    b = __shfl_sync(0xffffffffu, b, 0);
    const bool have = (b < NB);

    if (have) {
        SETUP_PTRS(i0, i1, i2, i3, b * 32);
        LOAD_CHUNK(i0, i1, i2, i3, 0, 0); CP_COMMIT();
        LOAD_CHUNK(i0, i1, i2, i3, 1, 1); CP_COMMIT();
        LOAD_CHUNK(i0, i1, i2, i3, 2, 2); CP_COMMIT();
        LOAD_CHUNK(i0, i1, i2, i3, 3, 3); CP_COMMIT();
    } else {
        CP_COMMIT(); CP_COMMIT(); CP_COMMIT(); CP_COMMIT();
    }

    // ---- 2) fold store + flag ----
    if (folder) {
        const int c  = fk >> 4;
        const int r  = fk & 15;
        const int kk = r >> 2;
        const int s2 = (r >> 1) & 1;
        const int w  = fk & 1;
        const int j  = fn >> 3;
        const int ln = (fn & 7) * 4 + kk;
        g_Wh[((((c * 8 + j) * 32) + ln) * 2 + s2) * 2 + w] =
            __float2half_rn(fsum * scale);
        __threadfence();
        __syncthreads();
        if (t == 0) atomicAdd(&g_fold, 1);
    }

    // bias into smem (local, independent of fold flag)
    if (t < 64) {
        float bsum = 0.f;
#pragma unroll
        for (int h = 0; h < 8; h++) bsum += bv[h * 64 + t];
        ((float*)(sm + 8192))[t] = bsum * scale;
    }

    // ---- 3) wait for fold completion, then stage W (32 KB, L2-hot) ----
    if (t == 0) {
        while (((volatile int*)&g_fold)[0] < 64) __nanosleep(20);
    }
    __syncthreads();
    __threadfence();
    {
        uint32_t dst = sb + t * 16;
        const char* src = (const char*)g_Wh + t * 16;
#pragma unroll
        for (int i = 0; i < 8; i++)
            CP_ASYNC16(dst + i * 4096, src + i * 4096);
        CP_COMMIT();
    }
    CP_WAIT(0);
    __syncthreads();

    const uint2* Wp = ((const uint2*)sm) + lane;
    const float* bias_s = (const float*)(sm + 8192);

    // ---- 4) mainloop: R8 structure, 5-stage ring (rolling counters) ----
    if (have) {
        SETUP_PTRS(s0, s1, s2, s3, b * 32);
        const float *c0p = s0, *c1p = s1, *c2p = s2, *c3p = s3;
        int ldst = 4;   // next load stage (chunks 0..3 occupy stages 0..3)
        int rdst = 0;   // next read stage

        for (;;) {
            int bn = NB;
            const float *n0p = c0p, *n1p = c1p, *n2p = c2p, *n3p = c3p;

            float acc0[8][4], acc1[8][4];
#pragma unroll
            for (int j = 0; j < 8; j++)
#pragma unroll
                for (int i = 0; i < 4; i++) { acc0[j][i] = 0.f; acc1[j][i] = 0.f; }

#pragma unroll
            for (int c = 0; c < 16; c++) {
                if (c == 11) {
                    if (lane == 0) bn = atomicAdd(&g_ctr, 1);
                    bn = __shfl_sync(0xffffffffu, bn, 0);
                }
                if (c == 12 && bn < NB) {
                    SETUP_PTRS(t0, t1, t2, t3, bn * 32);
                    n0p = t0; n1p = t1; n2p = t2; n3p = t3;
                }
                if (c < 12) {
                    LOAD_CHUNK(c0p, c1p, c2p, c3p, c + 4, ldst);
                    if (++ldst == NSTG) ldst = 0;
                } else if (bn < NB) {
                    LOAD_CHUNK(n0p, n1p, n2p, n3p, c - 12, ldst);
                    if (++ldst == NSTG) ldst = 0;
                }
                CP_COMMIT();
                CP_WAIT(4);

                const int st = rdst;
                if (++rdst == NSTG) rdst = 0;
                float4 q0 = ringp[st * 128];
                float4 q1 = ringp[st * 128 + 32];
                float4 q2 = ringp[st * 128 + 64];
                float4 q3 = ringp[st * 128 + 96];

                uint32_t a0, a1, a2, a3, b0, b1, b2, b3;
                PACK_F16X2(a0, q0.y, q0.x); PACK_F16X2(a1, q1.y, q1.x);
                PACK_F16X2(a2, q0.w, q0.z); PACK_F16X2(a3, q1.w, q1.z);
                PACK_F16X2(b0, q2.y, q2.x); PACK_F16X2(b1, q3.y, q3.x);
                PACK_F16X2(b2, q2.w, q2.z); PACK_F16X2(b3, q3.w, q3.z);
#pragma unroll
                for (int j = 0; j < 8; j++) {
                    uint2 w2 = Wp[(c * 8 + j) * 32];
                    MMA_F16(acc0[j], a0, a1, a2, a3, w2.x, w2.y);
                    MMA_F16(acc1[j], b0, b1, b2, b3, w2.x, w2.y);
                }
            }

            // epilogue: bias + store
            const int r0 = b * 32 + g;
            const int r1 = r0 + 8, r2 = r0 + 16, r3 = r0 + 24;
#pragma unroll
            for (int j = 0; j < 8; j++) {
                int col = j * 8 + kq * 2;
                float2 bb = *(const float2*)(bias_s + col);
                if (r0 < M)
                    *(float2*)(C + (size_t)r0 * 64 + col) =
                        make_float2(acc0[j][0] + bb.x, acc0[j][1] + bb.y);
                if (r1 < M)
                    *(float2*)(C + (size_t)r1 * 64 + col) =
                        make_float2(acc0[j][2] + bb.x, acc0[j][3] + bb.y);
                if (r2 < M)
                    *(float2*)(C + (size_t)r2 * 64 + col) =
                        make_float2(acc1[j][0] + bb.x, acc1[j][1] + bb.y);
                if (r3 < M)
                    *(float2*)(C + (size_t)r3 * 64 + col) =
                        make_float2(acc1[j][2] + bb.x, acc1[j][3] + bb.y);
            }

            if (bn >= NB) break;
            b = bn;
            c0p = n0p; c1p = n1p; c2p = n2p; c3p = n3p;
        }
    }
#undef LOAD_CHUNK
#undef SETUP_PTRS

    // ---- 5) last warp resets counters for the next graph replay ----
    if (lane == 0) {
        __threadfence();
        int d = atomicAdd(&g_done, 1);
        if (d == TOTW - 1) {
            g_ctr = 0;
            g_fold = 0;
            __threadfence();
            g_done = 0;
            __threadfence();
        }
    }
}

// ---------------- launch ----------------------------------------------------
extern "C" void kernel_launch(void* const* d_in, const int* in_sizes, int n_in,
                              void* d_out, int out_size) {
    const float* s_in = (const float*)d_in[1];
    const float* Wv   = (const float*)d_in[6];
    const float* bv   = (const float*)d_in[7];
    float* out = (float*)d_out;

    const int M = in_sizes[0] / 256;
    const int NB = (M + 31) / 32;

    const int SMEM = SMEM_U32 * 4;   // 114944 B -> 2 CTAs/SM
    cudaFuncSetAttribute(mma_all,
                         cudaFuncAttributeMaxDynamicSharedMemorySize, SMEM);
    mma_all<<<NCTA, 256, SMEM>>>(s_in, out, Wv, bv, M, NB, (float)M);
}

// round 13
// speedup vs baseline: 1.0417x; 1.0051x over previous
#include <cuda_runtime.h>
#include <cuda_fp16.h>
#include <math.h>
#include <cstdint>

// ============================================================================
// Round 13: out = s_in @ Wfold + bfold (algebraic collapse, R2 derivation).
// R8's two-kernel structure and byte-identical mainloop (best kernel: 25.3us)
// + clean PDL: prep releases dependents at entry; mma fires its A-prologue
// before griddepcontrol.wait, hiding prep entirely. Batch counter is reset
// device-side at end of mma (PDL makes prep-side reset racy).
// ============================================================================

#define EPS_F 1e-6f

__device__ __half g_Wh[16384];    // fragment-major f16 W (256k x 64n)
__device__ float g_bf[64];
__device__ int g_ctr  = 0;        // batch counter (reset by last warp of mma)
__device__ int g_done = 0;

// ---------------- prep: fold Wv over heads, f16-round, scatter --------------
// actual k = c*16 + kq*4 + s*2 + w  <->  hw col (kq*2 + s*8 + w) of step c
__global__ void prep_kernel(const float* __restrict__ Wv,
                            const float* __restrict__ bv, float nf) {
    asm volatile("griddepcontrol.launch_dependents;");
    const float scale = nf / (8.f * (nf + EPS_F));
    const int t = threadIdx.x;                 // 256
    const int k = blockIdx.x * 4 + (t >> 6);   // 0..255
    const int n = t & 63;

    float s = 0.f;
#pragma unroll
    for (int h = 0; h < 8; h++) s += Wv[k * 512 + h * 64 + n];
    float wf = s * scale;

    const int c  = k >> 4;
    const int r  = k & 15;
    const int kq = r >> 2;
    const int s2 = (r >> 1) & 1;
    const int w  = k & 1;
    const int j  = n >> 3;
    const int nn = n & 7;
    const int lane = nn * 4 + kq;
    g_Wh[((((c * 8 + j) * 32) + lane) * 2 + s2) * 2 + w] = __float2half_rn(wf);

    if (k == 0) {
        float b = 0.f;
#pragma unroll
        for (int h = 0; h < 8; h++) b += bv[h * 64 + n];
        g_bf[n] = b * scale;
    }
}

// ---------------- helpers ---------------------------------------------------
#define PACK_F16X2(d, hi, lo) \
    asm("cvt.rn.f16x2.f32 %0, %1, %2;" : "=r"(d) : "f"(hi), "f"(lo))

#define MMA_F16(c, a0, a1, a2, a3, b0, b1)                                      \
    asm volatile(                                                               \
        "mma.sync.aligned.m16n8k16.row.col.f32.f16.f16.f32 "                    \
        "{%0,%1,%2,%3}, {%4,%5,%6,%7}, {%8,%9}, {%0,%1,%2,%3};"                 \
        : "+f"((c)[0]), "+f"((c)[1]), "+f"((c)[2]), "+f"((c)[3])                \
        : "r"(a0), "r"(a1), "r"(a2), "r"(a3), "r"(b0), "r"(b1))

#define CP_ASYNC16(dst, src)                                                    \
    asm volatile("cp.async.cg.shared.global [%0], [%1], 16;"                    \
                 :: "r"(dst), "l"(src) : "memory")
#define CP_COMMIT()  asm volatile("cp.async.commit_group;" ::: "memory")
#define CP_WAIT(n)   asm volatile("cp.async.wait_group %0;" :: "n"(n) : "memory")

__device__ __forceinline__ uint32_t smem_u32(const void* p) {
    uint32_t a;
    asm("{ .reg .u64 t; cvta.to.shared.u64 t, %1; cvt.u32.u64 %0, t; }"
        : "=r"(a) : "l"(p));
    return a;
}

#define NCTA 296
#define TOTW (NCTA * 8)
// smem u32 layout: [0..8191] W frags | [8192..8255] bias | rings 8KB/warp
#define RING0_U32 8256
#define SMEM_U32  (RING0_U32 + 8 * 2048)    // 24640 u32 = 98560 B

// ---------------- main persistent GEMM: [M,256] @ [256,64] ------------------
__global__ __launch_bounds__(256, 2)
void mma_gemm(const float* __restrict__ A, float* __restrict__ C,
              int M, int NB) {
    extern __shared__ uint32_t sm[];
    const uint32_t sb = smem_u32(sm);

    const int t = threadIdx.x;
    const int wid = t >> 5;
    const int lane = t & 31;
    const int g  = lane >> 2;
    const int kq = lane & 3;

    // ring: 4 stages x 2048 B per warp; thread slot g*64 + kq*16 within stage
    const uint32_t ring0 = sb + RING0_U32 * 4 + wid * 8192 + g * 64 + kq * 16;
    const float4* ringp = (const float4*)((const char*)sm +
                          RING0_U32 * 4 + wid * 8192 + g * 64 + kq * 16);
    // ringp in float4 units: stage*128 + rowgrp*32

#define SETUP_PTRS(p0, p1, p2, p3, base)                                        \
    const float* p0 = A + (size_t)min((base) + g,      M - 1) * 256 + kq * 4;   \
    const float* p1 = A + (size_t)min((base) + g + 8,  M - 1) * 256 + kq * 4;   \
    const float* p2 = A + (size_t)min((base) + g + 16, M - 1) * 256 + kq * 4;   \
    const float* p3 = A + (size_t)min((base) + g + 24, M - 1) * 256 + kq * 4

#define LOAD_CHUNK(p0, p1, p2, p3, c, st) do {                                  \
        uint32_t d_ = ring0 + (st) * 2048;                                      \
        CP_ASYNC16(d_,        p0 + (c) * 16);                                   \
        CP_ASYNC16(d_ + 512,  p1 + (c) * 16);                                   \
        CP_ASYNC16(d_ + 1024, p2 + (c) * 16);                                   \
        CP_ASYNC16(d_ + 1536, p3 + (c) * 16);                                   \
    } while (0)

    // ---- 1) grab first batch + A prologue (independent of prep's W) ----
    int b;
    if (lane == 0) b = atomicAdd(&g_ctr, 1);
    b = __shfl_sync(0xffffffffu, b, 0);
    const bool have = (b < NB);

    if (have) {
        SETUP_PTRS(i0, i1, i2, i3, b * 32);
        LOAD_CHUNK(i0, i1, i2, i3, 0, 0); CP_COMMIT();
        LOAD_CHUNK(i0, i1, i2, i3, 1, 1); CP_COMMIT();
        LOAD_CHUNK(i0, i1, i2, i3, 2, 2); CP_COMMIT();
    } else {
        CP_COMMIT(); CP_COMMIT(); CP_COMMIT();
    }

    // ---- 2) wait for prep (PDL), then stage W (32 KB, L2-hot) ----
    asm volatile("griddepcontrol.wait;");
    {
        uint32_t dst = sb + t * 16;
        const char* src = (const char*)g_Wh + t * 16;
#pragma unroll
        for (int i = 0; i < 8; i++)
            CP_ASYNC16(dst + i * 4096, src + i * 4096);
        CP_COMMIT();
    }
    if (t < 64) ((float*)(sm + 8192))[t] = g_bf[t];
    CP_WAIT(0);
    __syncthreads();

    const uint2* Wp = ((const uint2*)sm) + lane;
    const float* bias_s = (const float*)(sm + 8192);

    // ---- 3) mainloop: identical to R8 ----
    if (have) {
        SETUP_PTRS(s0, s1, s2, s3, b * 32);
        const float *c0p = s0, *c1p = s1, *c2p = s2, *c3p = s3;

        for (;;) {
            int bn = NB;
            const float *n0p = c0p, *n1p = c1p, *n2p = c2p, *n3p = c3p;

            float acc0[8][4], acc1[8][4];
#pragma unroll
            for (int j = 0; j < 8; j++)
#pragma unroll
                for (int i = 0; i < 4; i++) { acc0[j][i] = 0.f; acc1[j][i] = 0.f; }

#pragma unroll
            for (int c = 0; c < 16; c++) {
                if (c == 12) {
                    if (lane == 0) bn = atomicAdd(&g_ctr, 1);
                    bn = __shfl_sync(0xffffffffu, bn, 0);
                }
                if (c == 13 && bn < NB) {
                    SETUP_PTRS(t0, t1, t2, t3, bn * 32);
                    n0p = t0; n1p = t1; n2p = t2; n3p = t3;
                }
                if (c < 13) {
                    LOAD_CHUNK(c0p, c1p, c2p, c3p, c + 3, (c + 3) & 3);
                } else if (bn < NB) {
                    LOAD_CHUNK(n0p, n1p, n2p, n3p, c - 13, (c + 3) & 3);
                }
                CP_COMMIT();
                CP_WAIT(3);

                const int st = c & 3;
                float4 q0 = ringp[st * 128];
                float4 q1 = ringp[st * 128 + 32];
                float4 q2 = ringp[st * 128 + 64];
                float4 q3 = ringp[st * 128 + 96];

                uint32_t a0, a1, a2, a3, b0, b1, b2, b3;
                PACK_F16X2(a0, q0.y, q0.x); PACK_F16X2(a1, q1.y, q1.x);
                PACK_F16X2(a2, q0.w, q0.z); PACK_F16X2(a3, q1.w, q1.z);
                PACK_F16X2(b0, q2.y, q2.x); PACK_F16X2(b1, q3.y, q3.x);
                PACK_F16X2(b2, q2.w, q2.z); PACK_F16X2(b3, q3.w, q3.z);
#pragma unroll
                for (int j = 0; j < 8; j++) {
                    uint2 w2 = Wp[(c * 8 + j) * 32];
                    MMA_F16(acc0[j], a0, a1, a2, a3, w2.x, w2.y);
                    MMA_F16(acc1[j], b0, b1, b2, b3, w2.x, w2.y);
                }
            }

            // epilogue: bias + store
            const int r0 = b * 32 + g;
            const int r1 = r0 + 8, r2 = r0 + 16, r3 = r0 + 24;
#pragma unroll
            for (int j = 0; j < 8; j++) {
                int col = j * 8 + kq * 2;
                float2 bb = *(const float2*)(bias_s + col);
                if (r0 < M)
                    *(float2*)(C + (size_t)r0 * 64 + col) =
                        make_float2(acc0[j][0] + bb.x, acc0[j][1] + bb.y);
                if (r1 < M)
                    *(float2*)(C + (size_t)r1 * 64 + col) =
                        make_float2(acc0[j][2] + bb.x, acc0[j][3] + bb.y);
                if (r2 < M)
                    *(float2*)(C + (size_t)r2 * 64 + col) =
                        make_float2(acc1[j][0] + bb.x, acc1[j][1] + bb.y);
                if (r3 < M)
                    *(float2*)(C + (size_t)r3 * 64 + col) =
                        make_float2(acc1[j][2] + bb.x, acc1[j][3] + bb.y);
            }

            if (bn >= NB) break;
            b = bn;
            c0p = n0p; c1p = n1p; c2p = n2p; c3p = n3p;
        }
    }
#undef LOAD_CHUNK
#undef SETUP_PTRS

    // ---- 4) last warp resets the counter for the next graph replay ----
    if (lane == 0) {
        __threadfence();
        int d = atomicAdd(&g_done, 1);
        if (d == TOTW - 1) {
            g_ctr = 0;
            __threadfence();
            g_done = 0;
            __threadfence();
        }
    }
}

// ---------------- launch ----------------------------------------------------
extern "C" void kernel_launch(void* const* d_in, const int* in_sizes, int n_in,
                              void* d_out, int out_size) {
    const float* s_in = (const float*)d_in[1];
    const float* Wv   = (const float*)d_in[6];
    const float* bv   = (const float*)d_in[7];
    float* out = (float*)d_out;

    const int M = in_sizes[0] / 256;
    const int NB = (M + 31) / 32;

    prep_kernel<<<64, 256>>>(Wv, bv, (float)M);

    const int SMEM = SMEM_U32 * 4;   // 98560 B -> 2 CTAs/SM
    cudaFuncSetAttribute(mma_gemm,
                         cudaFuncAttributeMaxDynamicSharedMemorySize, SMEM);

    cudaLaunchConfig_t cfg = {};
    cfg.gridDim = dim3(NCTA, 1, 1);
    cfg.blockDim = dim3(256, 1, 1);
    cfg.dynamicSmemBytes = SMEM;
    cudaLaunchAttribute attrs[1];
    attrs[0].id = cudaLaunchAttributeProgrammaticStreamSerialization;
    attrs[0].val.programmaticStreamSerializationAllowed = 1;
    cfg.attrs = attrs;
    cfg.numAttrs = 1;
    cudaLaunchKernelEx(&cfg, mma_gemm, s_in, out, M, NB);
}

// round 14
// speedup vs baseline: 1.1239x; 1.0789x over previous
#include <cuda_runtime.h>
#include <cuda_fp16.h>
#include <math.h>
#include <cstdint>

// ============================================================================
// Round 14: out = s_in @ Wfold + bfold (algebraic collapse, R2 derivation).
// fp16 m16n8k16 persistent warp-autonomous GEMM. Change vs R8 (best):
//  - stage = 16 rows x 128B: every cp.async instruction fetches 4 FULL
//    128-byte lines (contiguous per 8 lanes) instead of 8 x 64B half-lines
//  - XOR dst swizzle (seg ^ (row&1)*4) keeps consumer LDS conflict-free
//  - 16-row warp batches (NB=6250: 2.64/warp, 14% quantization vs 52%)
//  - 5-stage x 2KB per-warp ring, wait-depth 3 (~780cyc cover)
// W layout, MMA order, two-kernel launcher: identical to R8.
// ============================================================================

#define EPS_F 1e-6f

__device__ __half g_Wh[16384];    // fragment-major f16 W (256k x 64n)
__device__ float g_bf[64];
__device__ int g_ctr;

// ---------------- prep: fold Wv over heads, f16-round, scatter --------------
// actual k = c*16 + kq*4 + s*2 + w  <->  hw col (kq*2 + s*8 + w) of step c
__global__ void prep_kernel(const float* __restrict__ Wv,
                            const float* __restrict__ bv, float nf) {
    const float scale = nf / (8.f * (nf + EPS_F));
    const int t = threadIdx.x;                 // 256
    const int k = blockIdx.x * 4 + (t >> 6);   // 0..255
    const int n = t & 63;
    if (blockIdx.x == 0 && t == 0) g_ctr = 0;

    float s = 0.f;
#pragma unroll
    for (int h = 0; h < 8; h++) s += Wv[k * 512 + h * 64 + n];
    float wf = s * scale;

    const int c  = k >> 4;
    const int r  = k & 15;
    const int kq = r >> 2;
    const int s2 = (r >> 1) & 1;
    const int w  = k & 1;
    const int j  = n >> 3;
    const int nn = n & 7;
    const int lane = nn * 4 + kq;
    g_Wh[((((c * 8 + j) * 32) + lane) * 2 + s2) * 2 + w] = __float2half_rn(wf);

    if (k == 0) {
        float b = 0.f;
#pragma unroll
        for (int h = 0; h < 8; h++) b += bv[h * 64 + n];
        g_bf[n] = b * scale;
    }
}

// ---------------- helpers ---------------------------------------------------
#define PACK_F16X2(d, hi, lo) \
    asm("cvt.rn.f16x2.f32 %0, %1, %2;" : "=r"(d) : "f"(hi), "f"(lo))

#define MMA_F16(c, a0, a1, a2, a3, b0, b1)                                      \
    asm volatile(                                                               \
        "mma.sync.aligned.m16n8k16.row.col.f32.f16.f16.f32 "                    \
        "{%0,%1,%2,%3}, {%4,%5,%6,%7}, {%8,%9}, {%0,%1,%2,%3};"                 \
        : "+f"((c)[0]), "+f"((c)[1]), "+f"((c)[2]), "+f"((c)[3])                \
        : "r"(a0), "r"(a1), "r"(a2), "r"(a3), "r"(b0), "r"(b1))

#define CP_ASYNC16(dst, src)                                                    \
    asm volatile("cp.async.cg.shared.global [%0], [%1], 16;"                    \
                 :: "r"(dst), "l"(src) : "memory")
#define CP_COMMIT()  asm volatile("cp.async.commit_group;" ::: "memory")
#define CP_WAIT(n)   asm volatile("cp.async.wait_group %0;" :: "n"(n) : "memory")

__device__ __forceinline__ uint32_t smem_u32(const void* p) {
    uint32_t a;
    asm("{ .reg .u64 t; cvta.to.shared.u64 t, %1; cvt.u32.u64 %0, t; }"
        : "=r"(a) : "l"(p));
    return a;
}

#define NCTA 296
#define NSTG 5
// smem u32 layout: [0..8191] W frags | [8192..8255] bias | rings 10KB/warp
#define RING0_U32 8256
#define SMEM_U32  (RING0_U32 + 8 * (NSTG * 512))   // 28736 u32 = 114944 B

// ---------------- main persistent GEMM: [M,256] @ [256,64] ------------------
// 8 warps; 16-row warp batches; stage = 16 rows x 128B (2 k16-chunks).
__global__ __launch_bounds__(256, 2)
void mma_gemm(const float* __restrict__ A, float* __restrict__ C,
              int M, int NB) {
    extern __shared__ uint32_t sm[];
    const uint32_t sb = smem_u32(sm);

    const int t = threadIdx.x;
    const int wid = t >> 5;
    const int lane = t & 31;
    const int g  = lane >> 2;     // consumer row group 0..7
    const int kq = lane & 3;      // consumer k quad
    const int rof = lane >> 3;    // loader row-in-quad 0..3
    const int seg = lane & 7;     // loader 16B segment 0..7

    // loader per-lane constants
    const int swz = seg ^ ((rof & 1) << 2);
    const uint32_t dst_const = (uint32_t)(rof * 128 + swz * 16);
    // consumer per-lane byte offsets within a stage (sub = 0,1)
    const uint32_t cons0 = (uint32_t)(g * 128 + (((0 * 4 + kq) ^ ((g & 1) * 4)) * 16));
    const uint32_t cons1 = (uint32_t)(g * 128 + (((1 * 4 + kq) ^ ((g & 1) * 4)) * 16));

    const uint32_t ringb = sb + RING0_U32 * 4 + wid * (NSTG * 2048);
    const char* ringc = (const char*)sm + RING0_U32 * 4 + wid * (NSTG * 2048);

#define SETUP_PTR(p, base)                                                      \
    const float* p = A + (size_t)min((base) + rof, M - 1) * 256 + seg * 4

#define LOAD_STAGE(p, c2, st) do {                                              \
        uint32_t d_ = ringb + (uint32_t)(st) * 2048 + dst_const;                \
        const float* s_ = (p) + (c2) * 32;                                      \
        CP_ASYNC16(d_,        s_);                                              \
        CP_ASYNC16(d_ + 512,  s_ + 1024);                                       \
        CP_ASYNC16(d_ + 1024, s_ + 2048);                                       \
        CP_ASYNC16(d_ + 1536, s_ + 3072);                                       \
    } while (0)

    // ---- 1) grab first batch + 3-stage A prologue ----
    int b;
    if (lane == 0) b = atomicAdd(&g_ctr, 1);
    b = __shfl_sync(0xffffffffu, b, 0);
    const bool have = (b < NB);

    if (have) {
        SETUP_PTR(i0, b * 16);
        LOAD_STAGE(i0, 0, 0); CP_COMMIT();
        LOAD_STAGE(i0, 1, 1); CP_COMMIT();
        LOAD_STAGE(i0, 2, 2); CP_COMMIT();
    } else {
        CP_COMMIT(); CP_COMMIT(); CP_COMMIT();
    }

    // ---- 2) stage W (32 KB, L2-hot) + bias ----
    {
        uint32_t dst = sb + t * 16;
        const char* src = (const char*)g_Wh + t * 16;
#pragma unroll
        for (int i = 0; i < 8; i++)
            CP_ASYNC16(dst + i * 4096, src + i * 4096);
        CP_COMMIT();
    }
    if (t < 64) ((float*)(sm + 8192))[t] = g_bf[t];
    CP_WAIT(0);
    __syncthreads();

    const uint2* Wp = ((const uint2*)sm) + lane;
    const float* bias_s = (const float*)(sm + 8192);

    // ---- 3) mainloop: 8 stages per batch, rolling 5-stage ring ----
    if (have) {
        SETUP_PTR(s0, b * 16);
        const float* cp_ = s0;
        int ldst = 3;   // next load slot (prologue used 0..2)
        int rdst = 0;   // next read slot

        for (;;) {
            int bn = NB;
            const float* np_ = cp_;

            float acc[8][4];
#pragma unroll
            for (int j = 0; j < 8; j++)
#pragma unroll
                for (int i = 0; i < 4; i++) acc[j][i] = 0.f;

#pragma unroll
            for (int s = 0; s < 8; s++) {
                if (s == 4) {
                    if (lane == 0) bn = atomicAdd(&g_ctr, 1);
                    bn = __shfl_sync(0xffffffffu, bn, 0);
                }
                if (s == 5 && bn < NB) {
                    SETUP_PTR(t0, bn * 16);
                    np_ = t0;
                }
                if (s < 5) {
                    LOAD_STAGE(cp_, s + 3, ldst);
                    if (++ldst == NSTG) ldst = 0;
                } else if (bn < NB) {
                    LOAD_STAGE(np_, s - 5, ldst);
                    if (++ldst == NSTG) ldst = 0;
                }
                CP_COMMIT();
                CP_WAIT(3);

                const int st = rdst;
                if (++rdst == NSTG) rdst = 0;
                const char* stp = ringc + st * 2048;

                // sub = 0  (k-chunk c = s*2)
                {
                    float4 q0 = *(const float4*)(stp + cons0);
                    float4 q1 = *(const float4*)(stp + cons0 + 1024);
                    uint32_t a0, a1, a2, a3;
                    PACK_F16X2(a0, q0.y, q0.x); PACK_F16X2(a1, q1.y, q1.x);
                    PACK_F16X2(a2, q0.w, q0.z); PACK_F16X2(a3, q1.w, q1.z);
#pragma unroll
                    for (int j = 0; j < 8; j++) {
                        uint2 w2 = Wp[((s * 2 + 0) * 8 + j) * 32];
                        MMA_F16(acc[j], a0, a1, a2, a3, w2.x, w2.y);
                    }
                }
                // sub = 1  (k-chunk c = s*2 + 1)
                {
                    float4 q0 = *(const float4*)(stp + cons1);
                    float4 q1 = *(const float4*)(stp + cons1 + 1024);
                    uint32_t a0, a1, a2, a3;
                    PACK_F16X2(a0, q0.y, q0.x); PACK_F16X2(a1, q1.y, q1.x);
                    PACK_F16X2(a2, q0.w, q0.z); PACK_F16X2(a3, q1.w, q1.z);
#pragma unroll
                    for (int j = 0; j < 8; j++) {
                        uint2 w2 = Wp[((s * 2 + 1) * 8 + j) * 32];
                        MMA_F16(acc[j], a0, a1, a2, a3, w2.x, w2.y);
                    }
                }
            }

            // epilogue: bias + store (rows b*16+g, +8; cols j*8 + kq*2, +1)
            const int r0 = b * 16 + g;
            const int r1 = r0 + 8;
#pragma unroll
            for (int j = 0; j < 8; j++) {
                int col = j * 8 + kq * 2;
                float2 bb = *(const float2*)(bias_s + col);
                if (r0 < M)
                    *(float2*)(C + (size_t)r0 * 64 + col) =
                        make_float2(acc[j][0] + bb.x, acc[j][1] + bb.y);
                if (r1 < M)
                    *(float2*)(C + (size_t)r1 * 64 + col) =
                        make_float2(acc[j][2] + bb.x, acc[j][3] + bb.y);
            }

            if (bn >= NB) break;
            b = bn;
            cp_ = np_;
        }
    }
#undef LOAD_STAGE
#undef SETUP_PTR
}

// ---------------- launch ----------------------------------------------------
extern "C" void kernel_launch(void* const* d_in, const int* in_sizes, int n_in,
                              void* d_out, int out_size) {
    const float* s_in = (const float*)d_in[1];
    const float* Wv   = (const float*)d_in[6];
    const float* bv   = (const float*)d_in[7];
    float* out = (float*)d_out;

    const int M = in_sizes[0] / 256;
    const int NB = (M + 15) / 16;

    prep_kernel<<<64, 256>>>(Wv, bv, (float)M);

    const int SMEM = SMEM_U32 * 4;   // 114944 B -> 2 CTAs/SM
    cudaFuncSetAttribute(mma_gemm,
                         cudaFuncAttributeMaxDynamicSharedMemorySize, SMEM);
    mma_gemm<<<NCTA, 256, SMEM>>>(s_in, out, M, NB);
}